// round 15
// baseline (speedup 1.0000x reference)
#include <cuda_runtime.h>
#include <cuda_bf16.h>
#include <math.h>
#include <stdint.h>

typedef __nv_bfloat16 bf16;

#define BB   2
#define SS_  2048
#define DM   1024
#define NT   (BB*SS_)
#define NH   16
#define HD   64
#define DSTATE 128
#define DFF  4096

// ---------------- device scratch ----------------
__device__ __align__(256) bf16 g_qkv_hi[NT*3*DM], g_qkv_lo[NT*3*DM];
__device__ __align__(256) bf16 g_h_hi[NT*DM],     g_h_lo[NT*DM];
__device__ __align__(256) bf16 g_attn_hi[NT*DM],  g_attn_lo[NT*DM];
__device__ __align__(256) bf16 g_ff2_hi[NT*DFF],  g_ff2_lo[NT*DFF];
__device__ __align__(256) bf16 g_wqkvT_hi[3*DM*DM], g_wqkvT_lo[3*DM*DM];
__device__ __align__(256) bf16 g_woT_hi[DM*DM],   g_woT_lo[DM*DM];
__device__ __align__(256) bf16 g_gf1T_hi[2*DFF*DM], g_gf1T_lo[2*DFF*DM];
__device__ __align__(256) bf16 g_f2T_hi[DFF*DM],  g_f2T_lo[DFF*DM];
__device__ __align__(256) bf16 g_w1qT_hi[DSTATE*HD], g_w1qT_lo[DSTATE*HD];
__device__ __align__(256) bf16 g_w2qT_hi[HD*DSTATE], g_w2qT_lo[HD*DSTATE];
__device__ __align__(256) bf16 g_w1kT_hi[DSTATE*HD], g_w1kT_lo[DSTATE*HD];
__device__ __align__(256) bf16 g_w2kT_hi[HD*DSTATE], g_w2kT_lo[HD*DSTATE];

// ---------------- PTX helpers ----------------
__device__ __forceinline__ uint32_t s2u(const void* p) {
    uint32_t a;
    asm("{ .reg .u64 t; cvta.to.shared.u64 t, %1; cvt.u32.u64 %0, t; }" : "=r"(a) : "l"(p));
    return a;
}
#define CP16(d, s)   asm volatile("cp.async.cg.shared.global [%0], [%1], 16;" :: "r"(d), "l"(s))
#define CP_COMMIT()  asm volatile("cp.async.commit_group;" ::: "memory")
#define CP_WAIT1()   asm volatile("cp.async.wait_group 1;" ::: "memory")
#define CP_WAIT0()   asm volatile("cp.async.wait_group 0;" ::: "memory")

__device__ __forceinline__ void ldm_x4(uint32_t* r, uint32_t addr) {
    asm volatile("ldmatrix.sync.aligned.m8n8.x4.shared.b16 {%0,%1,%2,%3}, [%4];"
        : "=r"(r[0]), "=r"(r[1]), "=r"(r[2]), "=r"(r[3]) : "r"(addr));
}
__device__ __forceinline__ void ldm_x4t(uint32_t* r, uint32_t addr) {
    asm volatile("ldmatrix.sync.aligned.m8n8.x4.trans.shared.b16 {%0,%1,%2,%3}, [%4];"
        : "=r"(r[0]), "=r"(r[1]), "=r"(r[2]), "=r"(r[3]) : "r"(addr));
}
__device__ __forceinline__ void mma_bf16(float* d, const uint32_t* a, const uint32_t* b) {
    asm volatile("mma.sync.aligned.m16n8k16.row.col.f32.bf16.bf16.f32 "
        "{%0,%1,%2,%3}, {%4,%5,%6,%7}, {%8,%9}, {%0,%1,%2,%3};"
        : "+f"(d[0]), "+f"(d[1]), "+f"(d[2]), "+f"(d[3])
        : "r"(a[0]), "r"(a[1]), "r"(a[2]), "r"(a[3]), "r"(b[0]), "r"(b[1]));
}

// ---------------- misc ----------------
__device__ __forceinline__ float block_sum(float v, float* sbuf) {
    int lane = threadIdx.x & 31, w = threadIdx.x >> 5;
    #pragma unroll
    for (int o = 16; o; o >>= 1) v += __shfl_xor_sync(0xffffffffu, v, o);
    if (lane == 0) sbuf[w] = v;
    __syncthreads();
    if (w == 0) {
        v = (lane < 8) ? sbuf[lane] : 0.f;
        #pragma unroll
        for (int o = 4; o; o >>= 1) v += __shfl_xor_sync(0xffffffffu, v, o);
        if (lane == 0) sbuf[0] = v;
    }
    __syncthreads();
    float r = sbuf[0];
    __syncthreads();
    return r;
}
__device__ __forceinline__ void split_bf16(float x, bf16& h, bf16& l) {
    h = __float2bfloat16(x);
    l = __float2bfloat16(x - __bfloat162float(h));
}
__device__ __forceinline__ uint32_t pk(bf16 a, bf16 b) {
    return ((uint32_t)__bfloat16_as_ushort(b) << 16) | __bfloat16_as_ushort(a);
}

// ---------------- norm kernels ----------------
__global__ __launch_bounds__(256) void norm3_fused(
    const float* __restrict__ x,
    const float* __restrict__ w1, const float* __restrict__ w2, const float* __restrict__ w3,
    float* __restrict__ xout, bf16* __restrict__ h_hi, bf16* __restrict__ h_lo)
{
    __shared__ float sbuf[32];
    const int t = blockIdx.x;
    const int base = threadIdx.x * 4;
    float4 v  = *(const float4*)(x + (size_t)t*DM + base);
    float4 a1 = *(const float4*)(w1 + base);
    float4 a2 = *(const float4*)(w2 + base);
    float4 a3 = *(const float4*)(w3 + base);

    float ss = v.x*v.x + v.y*v.y + v.z*v.z + v.w*v.w;
    float r = rsqrtf(block_sum(ss, sbuf) * (1.f/DM) + 1e-6f);
    v.x += a1.x*v.x*r; v.y += a1.y*v.y*r; v.z += a1.z*v.z*r; v.w += a1.w*v.w*r;

    ss = v.x*v.x + v.y*v.y + v.z*v.z + v.w*v.w;
    r = rsqrtf(block_sum(ss, sbuf) * (1.f/DM) + 1e-6f);
    v.x += a2.x*v.x*r; v.y += a2.y*v.y*r; v.z += a2.z*v.z*r; v.w += a2.w*v.w*r;
    *(float4*)(xout + (size_t)t*DM + base) = v;

    ss = v.x*v.x + v.y*v.y + v.z*v.z + v.w*v.w;
    r = rsqrtf(block_sum(ss, sbuf) * (1.f/DM) + 1e-6f);
    float hv[4] = { a3.x*v.x*r, a3.y*v.y*r, a3.z*v.z*r, a3.w*v.w*r };
    __align__(8) bf16 hh[4], hl[4];
    #pragma unroll
    for (int i = 0; i < 4; i++) split_bf16(hv[i], hh[i], hl[i]);
    *(uint2*)(h_hi + (size_t)t*DM + base) = *(uint2*)hh;
    *(uint2*)(h_lo + (size_t)t*DM + base) = *(uint2*)hl;
}

__global__ __launch_bounds__(256) void rmsnorm_k(
    const float* __restrict__ x, const float* __restrict__ w,
    bf16* __restrict__ o_hi, bf16* __restrict__ o_lo)
{
    __shared__ float sbuf[32];
    const int t = blockIdx.x;
    const int base = threadIdx.x * 4;
    float4 v = *(const float4*)(x + (size_t)t*DM + base);
    float4 a = *(const float4*)(w + base);
    float ss = v.x*v.x + v.y*v.y + v.z*v.z + v.w*v.w;
    float r = rsqrtf(block_sum(ss, sbuf) * (1.f/DM) + 1e-6f);
    float ov[4] = { a.x*v.x*r, a.y*v.y*r, a.z*v.z*r, a.w*v.w*r };
    __align__(8) bf16 hh[4], hl[4];
    #pragma unroll
    for (int i = 0; i < 4; i++) split_bf16(ov[i], hh[i], hl[i]);
    *(uint2*)(o_hi + (size_t)t*DM + base) = *(uint2*)hh;
    *(uint2*)(o_lo + (size_t)t*DM + base) = *(uint2*)hl;
}

// ---------------- fused weight transpose + split ----------------
struct WAll {
    const float* src[11];
    bf16* th[11];
    bf16* tl[11];
};

__global__ __launch_bounds__(256) void wconv_all(WAll wa)
{
    __shared__ float t[64][65];
    const int id = blockIdx.x;
    int m, tt;
    if (id < 1024)      { m = id >> 8; tt = id & 255; }
    else if (id < 2048) { m = 4; tt = id - 1024; }
    else if (id < 3072) { m = 5; tt = id - 2048; }
    else if (id < 4096) { m = 6; tt = id - 3072; }
    else                { int i2 = id - 4096; m = 7 + (i2 >> 1); tt = i2 & 1; }
    const int K = (m == 6) ? DFF : (m == 8 || m == 10) ? DSTATE : (m == 7 || m == 9) ? HD : DM;
    const int N = (m == 4 || m == 5) ? DFF : (m == 7 || m == 9) ? DSTATE : (m == 8 || m == 10) ? HD : DM;
    const int ntx = N / 64;
    const int n0 = (tt % ntx) * 64, k0 = (tt / ntx) * 64;
    const float* W = wa.src[m];
    bf16* Th = wa.th[m];
    bf16* Tl = wa.tl[m];
    const bool ilv = (m == 4 || m == 5);
    const int foff = (m == 5) ? 1 : 0;

    const int tid = threadIdx.x;
    {
        const int r = tid >> 2, c0 = (tid & 3) * 16;
        const float* src = W + (size_t)(k0 + r)*N + n0 + c0;
        #pragma unroll
        for (int j = 0; j < 4; j++) {
            float4 vv = *(const float4*)(src + j*4);
            t[r][c0 + j*4 + 0] = vv.x; t[r][c0 + j*4 + 1] = vv.y;
            t[r][c0 + j*4 + 2] = vv.z; t[r][c0 + j*4 + 3] = vv.w;
        }
    }
    __syncthreads();
    {
        const int n = tid >> 2, ks = (tid & 3) * 16;
        uint32_t ph[8], pl[8];
        #pragma unroll
        for (int j = 0; j < 8; j++) {
            float a = t[ks + j*2][n], c = t[ks + j*2 + 1][n];
            bf16 ha, la, hc, lc;
            split_bf16(a, ha, la); split_bf16(c, hc, lc);
            ph[j] = pk(ha, hc); pl[j] = pk(la, lc);
        }
        const size_t row_out = ilv ? (size_t)(2*(n0 + n) + foff) : (size_t)(n0 + n);
        const size_t ou = (row_out*K + k0 + ks) >> 1;
        uint32_t* dh = (uint32_t*)Th + ou;
        uint32_t* dl = (uint32_t*)Tl + ou;
        *(uint4*)(dh)     = make_uint4(ph[0], ph[1], ph[2], ph[3]);
        *(uint4*)(dh + 4) = make_uint4(ph[4], ph[5], ph[6], ph[7]);
        *(uint4*)(dl)     = make_uint4(pl[0], pl[1], pl[2], pl[3]);
        *(uint4*)(dl + 4) = make_uint4(pl[4], pl[5], pl[6], pl[7]);
    }
}

// ---------------- bf16x3 GEMM via mma.sync (128x128, 2 CTAs/SM) ----------------
// EPI: 0 none | 1 +extra | 4 +bias+extra | 5 gate/fc1 interleaved
#define GSTAGE 32768
#define GSMEM  (3*GSTAGE)

__device__ __forceinline__ uint32_t swz(int row, int chunk) {
    return (uint32_t)(row*64 + ((chunk ^ (row & 3) ^ ((row >> 2) & 1)) << 4));
}

template<int EPI, int OSPLIT>
__global__ __launch_bounds__(256) void gemm_mma(
    const bf16* __restrict__ Ahi, const bf16* __restrict__ Alo,
    const bf16* __restrict__ Bhi, const bf16* __restrict__ Blo,
    const float* __restrict__ bias, const float* __restrict__ bias2,
    const float* __restrict__ extra,
    float* __restrict__ C, bf16* __restrict__ Chi, bf16* __restrict__ Clo,
    int N, int K)
{
    extern __shared__ char smem[];
    const uint32_t sb = s2u(smem);
    const int tid = threadIdx.x;
    const int lane = tid & 31, wid = tid >> 5;
    const int wm = wid >> 2, wn = wid & 3;
    const int row0 = blockIdx.y * 128, col0 = blockIdx.x * 128;
    const int nc = K / 32;

    const int lr = tid >> 1, lc = tid & 1;
    const uint32_t off0 = swz(lr, lc), off1 = swz(lr, lc + 2);
    const bf16* gAh = Ahi + (size_t)(row0 + lr)*K + lc*8;
    const bf16* gAl = Alo + (size_t)(row0 + lr)*K + lc*8;
    const bf16* gBh = Bhi + (size_t)(col0 + lr)*K + lc*8;
    const bf16* gBl = Blo + (size_t)(col0 + lr)*K + lc*8;

    #define GLOAD(st, kc) do { \
        const uint32_t s0 = sb + (uint32_t)(st)*GSTAGE; \
        const int ko = (kc)*32; \
        CP16(s0 +          off0, gAh + ko); CP16(s0 +          off1, gAh + ko + 16); \
        CP16(s0 +  8192 + off0, gAl + ko); CP16(s0 +  8192 + off1, gAl + ko + 16); \
        CP16(s0 + 16384 + off0, gBh + ko); CP16(s0 + 16384 + off1, gBh + ko + 16); \
        CP16(s0 + 24576 + off0, gBl + ko); CP16(s0 + 24576 + off1, gBl + ko + 16); \
    } while (0)

    const int arow = wm*64 + (lane & 15);
    const int abit = lane >> 4;
    const int brow = wn*32 + (lane & 7) + ((lane >> 4) & 1)*8;
    const int bbit = (lane >> 3) & 1;

    float acc[4][4][4];
    #pragma unroll
    for (int i = 0; i < 4; i++)
        #pragma unroll
        for (int j = 0; j < 4; j++)
            #pragma unroll
            for (int d2 = 0; d2 < 4; d2++) acc[i][j][d2] = 0.f;

    GLOAD(0, 0); CP_COMMIT();
    GLOAD(1, 1); CP_COMMIT();

    for (int kc = 0; kc < nc; kc++) {
        CP_WAIT1();
        __syncthreads();
        // prefetch next stage early: stage (kc+2)%3 == (kc-1)%3, whose readers
        // all passed the barrier above, so the write is race-free.
        if (kc + 2 < nc) { GLOAD((kc + 2) % 3, kc + 2); CP_COMMIT(); }
        const uint32_t s0 = sb + (uint32_t)(kc % 3)*GSTAGE;
        #pragma unroll
        for (int ks = 0; ks < 2; ks++) {
            uint32_t ah[4][4], al[4][4], bh[2][4], bl[2][4];
            #pragma unroll
            for (int mt = 0; mt < 4; mt++) {
                const uint32_t ao = swz(arow + mt*16, ks*2 + abit);
                ldm_x4(ah[mt], s0 + ao);
                ldm_x4(al[mt], s0 + 8192 + ao);
            }
            #pragma unroll
            for (int n2 = 0; n2 < 2; n2++) {
                const uint32_t bo = swz(brow + n2*16, ks*2 + bbit);
                ldm_x4(bh[n2], s0 + 16384 + bo);
                ldm_x4(bl[n2], s0 + 24576 + bo);
            }
            #pragma unroll
            for (int mt = 0; mt < 4; mt++)
                #pragma unroll
                for (int nt = 0; nt < 4; nt++) {
                    const uint32_t* ph = &bh[nt >> 1][(nt & 1)*2];
                    const uint32_t* pl = &bl[nt >> 1][(nt & 1)*2];
                    mma_bf16(acc[mt][nt], ah[mt], ph);
                    mma_bf16(acc[mt][nt], ah[mt], pl);
                    mma_bf16(acc[mt][nt], al[mt], ph);
                }
        }
    }
    #undef GLOAD

    const int erow = lane >> 2;
    const int ecol = (lane & 3)*2;
    #pragma unroll
    for (int mt = 0; mt < 4; mt++)
        #pragma unroll
        for (int hf = 0; hf < 2; hf++) {
            const int row = row0 + wm*64 + mt*16 + erow + hf*8;
            #pragma unroll
            for (int nt = 0; nt < 4; nt++) {
                const int col = col0 + wn*32 + nt*8 + ecol;
                float v0 = acc[mt][nt][hf*2 + 0];
                float v1 = acc[mt][nt][hf*2 + 1];
                if (EPI == 5) {
                    const int j = col >> 1;
                    float g = v0 + bias[j];
                    float f = v1 + bias2[j];
                    g = g / (1.f + __expf(-g));
                    const float rv = g * f;
                    bf16 h0, l0; split_bf16(rv, h0, l0);
                    const size_t po = (size_t)row * (size_t)(N >> 1) + j;
                    Chi[po] = h0; Clo[po] = l0;
                    continue;
                }
                const size_t ro = (size_t)row * N + col;
                if (EPI == 1) { float2 e = *(const float2*)(extra + ro); v0 += e.x; v1 += e.y; }
                if (EPI == 4) {
                    float2 e = *(const float2*)(extra + ro);
                    v0 += bias[col] + e.x; v1 += bias[col + 1] + e.y;
                }
                if (OSPLIT) {
                    bf16 h0, l0, h1, l1;
                    split_bf16(v0, h0, l0); split_bf16(v1, h1, l1);
                    *(uint32_t*)(Chi + ro) = pk(h0, h1);
                    *(uint32_t*)(Clo + ro) = pk(l0, l1);
                } else {
                    float2 o; o.x = v0; o.y = v1;
                    *(float2*)(C + ro) = o;
                }
            }
        }
}

// ---------------- tensor-core qk silu-mlp residual (2 CTAs/SM) ----------------
#define QM_X_H 0u
#define QM_X_L 18432u
#define QM_W1H 36864u
#define QM_W1L 55296u
#define QM_W2H 73728u
#define QM_W2L 91136u
#define QM_B1  108544u
#define QM_B2  109056u
#define QM_SMEM 109312

__global__ __launch_bounds__(256, 2) void qk_mlp_mma(
    bf16* __restrict__ qkvh, bf16* __restrict__ qkvl,
    const bf16* __restrict__ w1qh, const bf16* __restrict__ w1ql,
    const bf16* __restrict__ w2qh, const bf16* __restrict__ w2ql,
    const bf16* __restrict__ w1kh, const bf16* __restrict__ w1kl,
    const bf16* __restrict__ w2kh, const bf16* __restrict__ w2kl,
    const float* __restrict__ qb1, const float* __restrict__ qb2,
    const float* __restrict__ kb1, const float* __restrict__ kb2)
{
    extern __shared__ char sm_[];
    const uint32_t sb = s2u(sm_);
    const int tid = threadIdx.x, lane = tid & 31, wid = tid >> 5;
    const int t0 = blockIdx.x * 8;
    const int seg = blockIdx.y * 1024;
    const bf16* w1h = blockIdx.y ? w1kh : w1qh;
    const bf16* w1l = blockIdx.y ? w1kl : w1ql;
    const bf16* w2h = blockIdx.y ? w2kh : w2qh;
    const bf16* w2l = blockIdx.y ? w2kl : w2ql;
    const float* b1 = blockIdx.y ? kb1 : qb1;
    const float* b2 = blockIdx.y ? kb2 : qb2;

    {
        const int r = tid >> 1, half = tid & 1;
        const uint4* s1h = (const uint4*)(w1h + r*HD + half*32);
        const uint4* s1l = (const uint4*)(w1l + r*HD + half*32);
        uint4* d1h = (uint4*)(sm_ + QM_W1H + r*144 + half*64);
        uint4* d1l = (uint4*)(sm_ + QM_W1L + r*144 + half*64);
        #pragma unroll
        for (int j = 0; j < 4; j++) { d1h[j] = s1h[j]; d1l[j] = s1l[j]; }
    }
    {
        const int r = tid >> 2, q = tid & 3;
        const uint4* s2h = (const uint4*)(w2h + r*DSTATE + q*32);
        const uint4* s2l = (const uint4*)(w2l + r*DSTATE + q*32);
        uint4* d2h = (uint4*)(sm_ + QM_W2H + r*272 + q*64);
        uint4* d2l = (uint4*)(sm_ + QM_W2L + r*272 + q*64);
        #pragma unroll
        for (int j = 0; j < 4; j++) { d2h[j] = s2h[j]; d2l[j] = s2l[j]; }
    }
    if (tid < 128) *(float*)(sm_ + QM_B1 + tid*4) = b1[tid];
    if (tid < 64)  *(float*)(sm_ + QM_B2 + tid*4) = b2[tid];
    {
        const int r = tid >> 1, half = tid & 1;
        const size_t ga = (size_t)(t0 + (r >> 4))*3072 + seg + (size_t)(r & 15)*64 + half*32;
        const uint4* sxh = (const uint4*)(qkvh + ga);
        const uint4* sxl = (const uint4*)(qkvl + ga);
        uint4* dxh = (uint4*)(sm_ + QM_X_H + r*144 + half*64);
        uint4* dxl = (uint4*)(sm_ + QM_X_L + r*144 + half*64);
        #pragma unroll
        for (int j = 0; j < 4; j++) { dxh[j] = sxh[j]; dxl[j] = sxl[j]; }
    }
    __syncthreads();

    const int m0 = wid * 16;

    float s[16][4];
    #pragma unroll
    for (int i = 0; i < 16; i++)
        #pragma unroll
        for (int e = 0; e < 4; e++) s[i][e] = 0.f;

    #pragma unroll
    for (int ks = 0; ks < 4; ks++) {
        uint32_t xh4[4], xl4[4];
        const uint32_t ao = (uint32_t)((m0 + (lane & 15))*144 + ks*32 + (lane >> 4)*16);
        ldm_x4(xh4, sb + QM_X_H + ao);
        ldm_x4(xl4, sb + QM_X_L + ao);
        #pragma unroll
        for (int n2 = 0; n2 < 8; n2++) {
            uint32_t wh4[4], wl4[4];
            const uint32_t bo = (uint32_t)((n2*16 + (lane & 7) + ((lane >> 4) & 1)*8)*144
                                           + ks*32 + ((lane >> 3) & 1)*16);
            ldm_x4(wh4, sb + QM_W1H + bo);
            ldm_x4(wl4, sb + QM_W1L + bo);
            mma_bf16(s[n2*2],   xh4, &wh4[0]);
            mma_bf16(s[n2*2],   xh4, &wl4[0]);
            mma_bf16(s[n2*2],   xl4, &wh4[0]);
            mma_bf16(s[n2*2+1], xh4, &wh4[2]);
            mma_bf16(s[n2*2+1], xh4, &wl4[2]);
            mma_bf16(s[n2*2+1], xl4, &wh4[2]);
        }
    }

    #pragma unroll
    for (int nt = 0; nt < 16; nt++)
        #pragma unroll
        for (int e = 0; e < 4; e++) {
            const int col = nt*8 + (lane & 3)*2 + (e & 1);
            float v = s[nt][e] + *(const float*)(sm_ + QM_B1 + col*4);
            s[nt][e] = v / (1.f + __expf(-v));
        }

    float o[8][4];
    #pragma unroll
    for (int i = 0; i < 8; i++)
        #pragma unroll
        for (int e = 0; e < 4; e++) o[i][e] = 0.f;

    #pragma unroll
    for (int ks2 = 0; ks2 < 8; ks2++) {
        uint32_t pah[4], pal[4];
        {
            bf16 h0,l0,h1,l1;
            split_bf16(s[2*ks2][0],h0,l0);   split_bf16(s[2*ks2][1],h1,l1);
            pah[0] = pk(h0,h1); pal[0] = pk(l0,l1);
            split_bf16(s[2*ks2][2],h0,l0);   split_bf16(s[2*ks2][3],h1,l1);
            pah[1] = pk(h0,h1); pal[1] = pk(l0,l1);
            split_bf16(s[2*ks2+1][0],h0,l0); split_bf16(s[2*ks2+1][1],h1,l1);
            pah[2] = pk(h0,h1); pal[2] = pk(l0,l1);
            split_bf16(s[2*ks2+1][2],h0,l0); split_bf16(s[2*ks2+1][3],h1,l1);
            pah[3] = pk(h0,h1); pal[3] = pk(l0,l1);
        }
        #pragma unroll
        for (int n2 = 0; n2 < 4; n2++) {
            uint32_t wh4[4], wl4[4];
            const uint32_t bo = (uint32_t)((n2*16 + (lane & 7) + ((lane >> 4) & 1)*8)*272
                                           + ks2*32 + ((lane >> 3) & 1)*16);
            ldm_x4(wh4, sb + QM_W2H + bo);
            ldm_x4(wl4, sb + QM_W2L + bo);
            mma_bf16(o[n2*2],   pah, &wh4[0]);
            mma_bf16(o[n2*2],   pah, &wl4[0]);
            mma_bf16(o[n2*2],   pal, &wh4[0]);
            mma_bf16(o[n2*2+1], pah, &wh4[2]);
            mma_bf16(o[n2*2+1], pah, &wl4[2]);
            mma_bf16(o[n2*2+1], pal, &wh4[2]);
        }
    }

    #pragma unroll
    for (int nt = 0; nt < 8; nt++)
        #pragma unroll
        for (int hf = 0; hf < 2; hf++) {
            const int rl = (lane >> 2) + hf*8;
            const int c0 = nt*8 + (lane & 3)*2;
            const int rX = m0 + rl;
            const float rs0 = __bfloat162float(*(const bf16*)(sm_ + QM_X_H + rX*144 + c0*2))
                            + __bfloat162float(*(const bf16*)(sm_ + QM_X_L + rX*144 + c0*2));
            const float rs1 = __bfloat162float(*(const bf16*)(sm_ + QM_X_H + rX*144 + c0*2 + 2))
                            + __bfloat162float(*(const bf16*)(sm_ + QM_X_L + rX*144 + c0*2 + 2));
            const float v0 = o[nt][hf*2 + 0] + *(const float*)(sm_ + QM_B2 + c0*4)     + rs0;
            const float v1 = o[nt][hf*2 + 1] + *(const float*)(sm_ + QM_B2 + c0*4 + 4) + rs1;
            bf16 h0, l0, h1, l1;
            split_bf16(v0, h0, l0); split_bf16(v1, h1, l1);
            const size_t ga = (size_t)(t0 + wid)*3072 + seg + (size_t)rl*64 + c0;
            *(uint32_t*)(qkvh + ga) = pk(h0, h1);
            *(uint32_t*)(qkvl + ga) = pk(l0, l1);
        }
}

// ---------------- pipelined tensor-core flash attention ----------------
#define FA_QH 0u
#define FA_QL 18432u
#define FA_S0 36864u
#define FA_STG 36864u
#define FA_SMEM 110592

__global__ __launch_bounds__(256, 2) void flash_mma(
    const bf16* __restrict__ QKVh, const bf16* __restrict__ QKVl,
    bf16* __restrict__ Ohi, bf16* __restrict__ Olo)
{
    extern __shared__ char sm_[];
    const uint32_t sb = s2u(sm_);
    const int tid = threadIdx.x;
    const int lane = tid & 31, wid = tid >> 5;
    const int qt = (int)gridDim.x - 1 - (int)blockIdx.x;
    const int h = blockIdx.y, b = blockIdx.z;
    const int qb = qt * 128;
    const int m0 = wid * 16;

    {
        const int r = tid >> 1;
        const int half = tid & 1;
        const size_t go = (size_t)(b*SS_ + qb + r)*3072 + h*64 + half*32;
        const uint4* srcH = (const uint4*)(QKVh + go);
        const uint4* srcL = (const uint4*)(QKVl + go);
        uint4* dstH = (uint4*)(sm_ + FA_QH + r*144 + half*64);
        uint4* dstL = (uint4*)(sm_ + FA_QL + r*144 + half*64);
        #pragma unroll
        for (int j = 0; j < 4; j++) { dstH[j] = srcH[j]; dstL[j] = srcL[j]; }
    }

    const int klr = tid >> 2, klq = tid & 3;
    #define LOADKV(st, kjj) do { \
        const uint32_t s0 = sb + FA_S0 + (uint32_t)(st)*FA_STG; \
        const uint32_t d = (uint32_t)(klr*144 + klq*32); \
        const size_t gk = (size_t)(b*SS_ + (kjj)*64 + klr)*3072 + 1024 + h*64 + klq*16; \
        CP16(s0 + d,               QKVh + gk);        CP16(s0 + d + 16,          QKVh + gk + 8); \
        CP16(s0 + 9216u + d,       QKVl + gk);        CP16(s0 + 9216u + d + 16,  QKVl + gk + 8); \
        CP16(s0 + 18432u + d,      QKVh + gk + 1024); CP16(s0 + 18432u + d + 16, QKVh + gk + 1032); \
        CP16(s0 + 27648u + d,      QKVl + gk + 1024); CP16(s0 + 27648u + d + 16, QKVl + gk + 1032); \
    } while (0)

    float mstate[2] = {-1e30f, -1e30f};
    float lsum[2]   = {0.f, 0.f};
    float o[8][4];
    #pragma unroll
    for (int i = 0; i < 8; i++)
        #pragma unroll
        for (int e = 0; e < 4; e++) o[i][e] = 0.f;

    const int nk = 2*qt + 2;
    LOADKV(0, 0); CP_COMMIT();

    for (int kj = 0; kj < nk; kj++) {
        CP_WAIT0();
        __syncthreads();
        if (kj + 1 < nk) { LOADKV((kj + 1) & 1, kj + 1); CP_COMMIT(); }
        const uint32_t st = sb + FA_S0 + (uint32_t)(kj & 1)*FA_STG;

        if (kj*64 <= qb + m0 + 15) {
            float s[8][4];
            #pragma unroll
            for (int i = 0; i < 8; i++)
                #pragma unroll
                for (int e = 0; e < 4; e++) s[i][e] = 0.f;

            #pragma unroll
            for (int ks = 0; ks < 4; ks++) {
                uint32_t qh4[4], ql4[4];
                const uint32_t ao = (uint32_t)((m0 + (lane & 15))*144 + ks*32 + (lane >> 4)*16);
                ldm_x4(qh4, sb + FA_QH + ao);
                ldm_x4(ql4, sb + FA_QL + ao);
                #pragma unroll
                for (int n2 = 0; n2 < 4; n2++) {
                    uint32_t kh4[4], kl4[4];
                    const uint32_t bo = (uint32_t)((n2*16 + (lane & 7) + ((lane >> 4) & 1)*8)*144
                                                   + ks*32 + ((lane >> 3) & 1)*16);
                    ldm_x4(kh4, st + bo);
                    ldm_x4(kl4, st + 9216u + bo);
                    mma_bf16(s[n2*2],   qh4, &kh4[0]);
                    mma_bf16(s[n2*2],   qh4, &kl4[0]);
                    mma_bf16(s[n2*2],   ql4, &kh4[0]);
                    mma_bf16(s[n2*2+1], qh4, &kh4[2]);
                    mma_bf16(s[n2*2+1], qh4, &kl4[2]);
                    mma_bf16(s[n2*2+1], ql4, &kh4[2]);
                }
            }

            const bool need_mask = (kj*64 + 63 > qb + m0);
            #pragma unroll
            for (int nt = 0; nt < 8; nt++)
                #pragma unroll
                for (int e = 0; e < 4; e++) {
                    float val = s[nt][e] * 0.125f;
                    if (need_mask) {
                        const int col = kj*64 + nt*8 + (lane & 3)*2 + (e & 1);
                        const int row = qb + m0 + (lane >> 2) + (e >> 1)*8;
                        if (col > row) val = -1e30f;
                    }
                    s[nt][e] = val;
                }

            float mx[2] = {-1e30f, -1e30f};
            #pragma unroll
            for (int nt = 0; nt < 8; nt++) {
                mx[0] = fmaxf(mx[0], fmaxf(s[nt][0], s[nt][1]));
                mx[1] = fmaxf(mx[1], fmaxf(s[nt][2], s[nt][3]));
            }
            #pragma unroll
            for (int hf = 0; hf < 2; hf++) {
                mx[hf] = fmaxf(mx[hf], __shfl_xor_sync(0xffffffffu, mx[hf], 1));
                mx[hf] = fmaxf(mx[hf], __shfl_xor_sync(0xffffffffu, mx[hf], 2));
            }
            float al2[2];
            #pragma unroll
            for (int hf = 0; hf < 2; hf++) {
                const float mn = fmaxf(fmaxf(mstate[hf], mx[hf]), -1e20f);
                al2[hf] = __expf(mstate[hf] - mn);
                mstate[hf] = mn;
            }
            float sum[2] = {0.f, 0.f};
            #pragma unroll
            for (int nt = 0; nt < 8; nt++)
                #pragma unroll
                for (int e = 0; e < 4; e++) {
                    const float p = __expf(s[nt][e] - mstate[e >> 1]);
                    s[nt][e] = p;
                    sum[e >> 1] += p;
                }
            #pragma unroll
            for (int hf = 0; hf < 2; hf++) {
                sum[hf] += __shfl_xor_sync(0xffffffffu, sum[hf], 1);
                sum[hf] += __shfl_xor_sync(0xffffffffu, sum[hf], 2);
                lsum[hf] = lsum[hf]*al2[hf] + sum[hf];
            }
            #pragma unroll
            for (int nt = 0; nt < 8; nt++)
                #pragma unroll
                for (int e = 0; e < 4; e++) o[nt][e] *= al2[e >> 1];

            #pragma unroll
            for (int ks2 = 0; ks2 < 4; ks2++) {
                uint32_t pah[4], pal[4];
                {
                    bf16 h0,l0,h1,l1;
                    split_bf16(s[2*ks2][0],h0,l0);   split_bf16(s[2*ks2][1],h1,l1);
                    pah[0] = pk(h0,h1); pal[0] = pk(l0,l1);
                    split_bf16(s[2*ks2][2],h0,l0);   split_bf16(s[2*ks2][3],h1,l1);
                    pah[1] = pk(h0,h1); pal[1] = pk(l0,l1);
                    split_bf16(s[2*ks2+1][0],h0,l0); split_bf16(s[2*ks2+1][1],h1,l1);
                    pah[2] = pk(h0,h1); pal[2] = pk(l0,l1);
                    split_bf16(s[2*ks2+1][2],h0,l0); split_bf16(s[2*ks2+1][3],h1,l1);
                    pah[3] = pk(h0,h1); pal[3] = pk(l0,l1);
                }
                #pragma unroll
                for (int dn2 = 0; dn2 < 4; dn2++) {
                    uint32_t vh4[4], vl4[4];
                    const uint32_t vo = (uint32_t)((ks2*16 + (lane & 7) + ((lane >> 3) & 1)*8)*144
                                                   + (dn2*16 + ((lane >> 4) & 1)*8)*2);
                    ldm_x4t(vh4, st + 18432u + vo);
                    ldm_x4t(vl4, st + 27648u + vo);
                    mma_bf16(o[dn2*2],   pah, &vh4[0]);
                    mma_bf16(o[dn2*2],   pah, &vl4[0]);
                    mma_bf16(o[dn2*2],   pal, &vh4[0]);
                    mma_bf16(o[dn2*2+1], pah, &vh4[2]);
                    mma_bf16(o[dn2*2+1], pah, &vl4[2]);
                    mma_bf16(o[dn2*2+1], pal, &vh4[2]);
                }
            }
        }
    }
    #undef LOADKV

    const float inv0 = 1.f / lsum[0];
    const float inv1 = 1.f / lsum[1];
    #pragma unroll
    for (int nt = 0; nt < 8; nt++)
        #pragma unroll
        for (int hf = 0; hf < 2; hf++) {
            const float inv = hf ? inv1 : inv0;
            const float v0 = o[nt][hf*2 + 0] * inv;
            const float v1 = o[nt][hf*2 + 1] * inv;
            bf16 h0, l0, h1, l1;
            split_bf16(v0, h0, l0); split_bf16(v1, h1, l1);
            const int row = qb + m0 + (lane >> 2) + hf*8;
            const int d0 = nt*8 + (lane & 3)*2;
            const size_t ro = ((size_t)(b*SS_ + row)*NH + h)*HD + d0;
            *(uint32_t*)(Ohi + ro) = pk(h0, h1);
            *(uint32_t*)(Olo + ro) = pk(l0, l1);
        }
}

// ---------------- launcher ----------------
extern "C" void kernel_launch(void* const* d_in, const int* in_sizes, int n_in,
                              void* d_out, int out_size)
{
    const float* x       = (const float*)d_in[0];
    const float* norm1_w = (const float*)d_in[2];
    const float* norm2_w = (const float*)d_in[3];
    const float* norm3_w = (const float*)d_in[4];
    const float* mlpn_w  = (const float*)d_in[5];
    const float* wq      = (const float*)d_in[6];
    const float* wk      = (const float*)d_in[7];
    const float* wv      = (const float*)d_in[8];
    const float* wo      = (const float*)d_in[9];
    const float* qs_w1   = (const float*)d_in[10];
    const float* qs_b1   = (const float*)d_in[11];
    const float* qs_w2   = (const float*)d_in[12];
    const float* qs_b2   = (const float*)d_in[13];
    const float* ks_w1   = (const float*)d_in[14];
    const float* ks_b1   = (const float*)d_in[15];
    const float* ks_w2   = (const float*)d_in[16];
    const float* ks_b2   = (const float*)d_in[17];
    const float* fc1_w   = (const float*)d_in[18];
    const float* fc1_b   = (const float*)d_in[19];
    const float* fc2_w   = (const float*)d_in[20];
    const float* fc2_b   = (const float*)d_in[21];
    const float* gate_w  = (const float*)d_in[22];
    const float* gate_b  = (const float*)d_in[23];
    float* out = (float*)d_out;

    bf16 *qkvh, *qkvl, *hh, *hl, *ah, *al, *f2h, *f2l;
    bf16 *wqkvh, *wqkvl, *woh, *wol, *gf1h, *gf1l, *fch, *fcl;
    bf16 *w1qh, *w1ql, *w2qh, *w2ql, *w1kh, *w1kl, *w2kh, *w2kl;
    cudaGetSymbolAddress((void**)&qkvh, g_qkv_hi);   cudaGetSymbolAddress((void**)&qkvl, g_qkv_lo);
    cudaGetSymbolAddress((void**)&hh,  g_h_hi);      cudaGetSymbolAddress((void**)&hl,  g_h_lo);
    cudaGetSymbolAddress((void**)&ah,  g_attn_hi);   cudaGetSymbolAddress((void**)&al,  g_attn_lo);
    cudaGetSymbolAddress((void**)&f2h, g_ff2_hi);    cudaGetSymbolAddress((void**)&f2l, g_ff2_lo);
    cudaGetSymbolAddress((void**)&wqkvh, g_wqkvT_hi); cudaGetSymbolAddress((void**)&wqkvl, g_wqkvT_lo);
    cudaGetSymbolAddress((void**)&woh, g_woT_hi);    cudaGetSymbolAddress((void**)&wol, g_woT_lo);
    cudaGetSymbolAddress((void**)&gf1h, g_gf1T_hi);  cudaGetSymbolAddress((void**)&gf1l, g_gf1T_lo);
    cudaGetSymbolAddress((void**)&fch, g_f2T_hi);    cudaGetSymbolAddress((void**)&fcl, g_f2T_lo);
    cudaGetSymbolAddress((void**)&w1qh, g_w1qT_hi);  cudaGetSymbolAddress((void**)&w1ql, g_w1qT_lo);
    cudaGetSymbolAddress((void**)&w2qh, g_w2qT_hi);  cudaGetSymbolAddress((void**)&w2ql, g_w2qT_lo);
    cudaGetSymbolAddress((void**)&w1kh, g_w1kT_hi);  cudaGetSymbolAddress((void**)&w1kl, g_w1kT_lo);
    cudaGetSymbolAddress((void**)&w2kh, g_w2kT_hi);  cudaGetSymbolAddress((void**)&w2kl, g_w2kT_lo);

    cudaFuncSetAttribute(gemm_mma<0,1>, cudaFuncAttributeMaxDynamicSharedMemorySize, GSMEM);
    cudaFuncSetAttribute(gemm_mma<1,0>, cudaFuncAttributeMaxDynamicSharedMemorySize, GSMEM);
    cudaFuncSetAttribute(gemm_mma<5,0>, cudaFuncAttributeMaxDynamicSharedMemorySize, GSMEM);
    cudaFuncSetAttribute(gemm_mma<4,0>, cudaFuncAttributeMaxDynamicSharedMemorySize, GSMEM);
    cudaFuncSetAttribute(qk_mlp_mma, cudaFuncAttributeMaxDynamicSharedMemorySize, QM_SMEM);
    cudaFuncSetAttribute(flash_mma, cudaFuncAttributeMaxDynamicSharedMemorySize, FA_SMEM);

    // launch 1: all weight converts
    WAll wa;
    wa.src[0] = wq;     wa.th[0] = wqkvh;           wa.tl[0] = wqkvl;
    wa.src[1] = wk;     wa.th[1] = wqkvh + DM*DM;   wa.tl[1] = wqkvl + DM*DM;
    wa.src[2] = wv;     wa.th[2] = wqkvh + 2*DM*DM; wa.tl[2] = wqkvl + 2*DM*DM;
    wa.src[3] = wo;     wa.th[3] = woh;             wa.tl[3] = wol;
    wa.src[4] = gate_w; wa.th[4] = gf1h;            wa.tl[4] = gf1l;
    wa.src[5] = fc1_w;  wa.th[5] = gf1h;            wa.tl[5] = gf1l;
    wa.src[6] = fc2_w;  wa.th[6] = fch;             wa.tl[6] = fcl;
    wa.src[7] = qs_w1;  wa.th[7] = w1qh;            wa.tl[7] = w1ql;
    wa.src[8] = qs_w2;  wa.th[8] = w2qh;            wa.tl[8] = w2ql;
    wa.src[9] = ks_w1;  wa.th[9] = w1kh;            wa.tl[9] = w1kl;
    wa.src[10] = ks_w2; wa.th[10] = w2kh;           wa.tl[10] = w2kl;
    wconv_all<<<4104, 256>>>(wa);

    // launch 2: mamba stages + pre-attn norm
    norm3_fused<<<NT, 256>>>(x, norm1_w, norm2_w, norm3_w, out, hh, hl);

    // launch 3: fused qkv projection -> token-major [NT, 3072] hi/lo
    gemm_mma<0,1><<<dim3(3*DM/128, NT/128), 256, GSMEM>>>(
        hh, hl, wqkvh, wqkvl, nullptr, nullptr, nullptr, nullptr, qkvh, qkvl, 3*DM, DM);

    // launch 4: per-head SiLU-MLP residual on q,k (tensor cores)
    qk_mlp_mma<<<dim3(NT/8, 2), 256, QM_SMEM>>>(qkvh, qkvl,
        w1qh, w1ql, w2qh, w2ql, w1kh, w1kl, w2kh, w2kl,
        qs_b1, qs_b2, ks_b1, ks_b2);

    // launch 5: causal attention (pipelined)
    flash_mma<<<dim3(SS_/128, NH, BB), 256, FA_SMEM>>>(qkvh, qkvl, ah, al);

    // launch 6: out projection + residual
    gemm_mma<1,0><<<dim3(DM/128, NT/128), 256, GSMEM>>>(
        ah, al, woh, wol, nullptr, nullptr, out, out, nullptr, nullptr, DM, DM);

    // launch 7: mlp norm
    rmsnorm_k<<<NT, 256>>>(out, mlpn_w, hh, hl);

    // launch 8: fused gate+fc1+silu-mul -> f2 hi/lo
    gemm_mma<5,0><<<dim3(2*DFF/128, NT/128), 256, GSMEM>>>(
        hh, hl, gf1h, gf1l, gate_b, fc1_b, nullptr, nullptr, f2h, f2l, 2*DFF, DM);

    // launch 9: fc2 + bias + residual
    gemm_mma<4,0><<<dim3(DM/128, NT/128), 256, GSMEM>>>(
        f2h, f2l, fch, fcl, fc2_b, nullptr, out, out, nullptr, nullptr, DM, DFF);
}

// round 16
// speedup vs baseline: 1.6592x; 1.6592x over previous
#include <cuda_runtime.h>
#include <cuda_bf16.h>
#include <math.h>
#include <stdint.h>

typedef __nv_bfloat16 bf16;

#define BB   2
#define SS_  2048
#define DM   1024
#define NT   (BB*SS_)
#define NH   16
#define HD   64
#define DSTATE 128
#define DFF  4096

// ---------------- device scratch ----------------
__device__ __align__(256) bf16 g_qkv_hi[NT*3*DM], g_qkv_lo[NT*3*DM];
__device__ __align__(256) bf16 g_h_hi[NT*DM],     g_h_lo[NT*DM];
__device__ __align__(256) bf16 g_attn_hi[NT*DM],  g_attn_lo[NT*DM];
__device__ __align__(256) bf16 g_ff2_hi[NT*DFF],  g_ff2_lo[NT*DFF];
__device__ __align__(256) bf16 g_wqkvT_hi[3*DM*DM], g_wqkvT_lo[3*DM*DM];
__device__ __align__(256) bf16 g_woT_hi[DM*DM],   g_woT_lo[DM*DM];
__device__ __align__(256) bf16 g_gf1T_hi[2*DFF*DM], g_gf1T_lo[2*DFF*DM];
__device__ __align__(256) bf16 g_f2T_hi[DFF*DM],  g_f2T_lo[DFF*DM];
__device__ __align__(256) bf16 g_w1qT_hi[DSTATE*HD], g_w1qT_lo[DSTATE*HD];
__device__ __align__(256) bf16 g_w2qT_hi[HD*DSTATE], g_w2qT_lo[HD*DSTATE];
__device__ __align__(256) bf16 g_w1kT_hi[DSTATE*HD], g_w1kT_lo[DSTATE*HD];
__device__ __align__(256) bf16 g_w2kT_hi[HD*DSTATE], g_w2kT_lo[HD*DSTATE];

// ---------------- PTX helpers ----------------
__device__ __forceinline__ uint32_t s2u(const void* p) {
    uint32_t a;
    asm("{ .reg .u64 t; cvta.to.shared.u64 t, %1; cvt.u32.u64 %0, t; }" : "=r"(a) : "l"(p));
    return a;
}
#define CP16(d, s)   asm volatile("cp.async.cg.shared.global [%0], [%1], 16;" :: "r"(d), "l"(s))
#define CP_COMMIT()  asm volatile("cp.async.commit_group;" ::: "memory")
#define CP_WAIT1()   asm volatile("cp.async.wait_group 1;" ::: "memory")
#define CP_WAIT0()   asm volatile("cp.async.wait_group 0;" ::: "memory")

__device__ __forceinline__ void ldm_x4(uint32_t* r, uint32_t addr) {
    asm volatile("ldmatrix.sync.aligned.m8n8.x4.shared.b16 {%0,%1,%2,%3}, [%4];"
        : "=r"(r[0]), "=r"(r[1]), "=r"(r[2]), "=r"(r[3]) : "r"(addr));
}
__device__ __forceinline__ void ldm_x4t(uint32_t* r, uint32_t addr) {
    asm volatile("ldmatrix.sync.aligned.m8n8.x4.trans.shared.b16 {%0,%1,%2,%3}, [%4];"
        : "=r"(r[0]), "=r"(r[1]), "=r"(r[2]), "=r"(r[3]) : "r"(addr));
}
__device__ __forceinline__ void mma_bf16(float* d, const uint32_t* a, const uint32_t* b) {
    asm volatile("mma.sync.aligned.m16n8k16.row.col.f32.bf16.bf16.f32 "
        "{%0,%1,%2,%3}, {%4,%5,%6,%7}, {%8,%9}, {%0,%1,%2,%3};"
        : "+f"(d[0]), "+f"(d[1]), "+f"(d[2]), "+f"(d[3])
        : "r"(a[0]), "r"(a[1]), "r"(a[2]), "r"(a[3]), "r"(b[0]), "r"(b[1]));
}

// ---------------- misc ----------------
__device__ __forceinline__ float block_sum(float v, float* sbuf) {
    int lane = threadIdx.x & 31, w = threadIdx.x >> 5;
    #pragma unroll
    for (int o = 16; o; o >>= 1) v += __shfl_xor_sync(0xffffffffu, v, o);
    if (lane == 0) sbuf[w] = v;
    __syncthreads();
    if (w == 0) {
        v = (lane < 8) ? sbuf[lane] : 0.f;
        #pragma unroll
        for (int o = 4; o; o >>= 1) v += __shfl_xor_sync(0xffffffffu, v, o);
        if (lane == 0) sbuf[0] = v;
    }
    __syncthreads();
    float r = sbuf[0];
    __syncthreads();
    return r;
}
__device__ __forceinline__ void split_bf16(float x, bf16& h, bf16& l) {
    h = __float2bfloat16(x);
    l = __float2bfloat16(x - __bfloat162float(h));
}
__device__ __forceinline__ uint32_t pk(bf16 a, bf16 b) {
    return ((uint32_t)__bfloat16_as_ushort(b) << 16) | __bfloat16_as_ushort(a);
}

// ---------------- norm kernels ----------------
__global__ __launch_bounds__(256) void norm3_fused(
    const float* __restrict__ x,
    const float* __restrict__ w1, const float* __restrict__ w2, const float* __restrict__ w3,
    float* __restrict__ xout, bf16* __restrict__ h_hi, bf16* __restrict__ h_lo)
{
    __shared__ float sbuf[32];
    const int t = blockIdx.x;
    const int base = threadIdx.x * 4;
    float4 v  = *(const float4*)(x + (size_t)t*DM + base);
    float4 a1 = *(const float4*)(w1 + base);
    float4 a2 = *(const float4*)(w2 + base);
    float4 a3 = *(const float4*)(w3 + base);

    float ss = v.x*v.x + v.y*v.y + v.z*v.z + v.w*v.w;
    float r = rsqrtf(block_sum(ss, sbuf) * (1.f/DM) + 1e-6f);
    v.x += a1.x*v.x*r; v.y += a1.y*v.y*r; v.z += a1.z*v.z*r; v.w += a1.w*v.w*r;

    ss = v.x*v.x + v.y*v.y + v.z*v.z + v.w*v.w;
    r = rsqrtf(block_sum(ss, sbuf) * (1.f/DM) + 1e-6f);
    v.x += a2.x*v.x*r; v.y += a2.y*v.y*r; v.z += a2.z*v.z*r; v.w += a2.w*v.w*r;
    *(float4*)(xout + (size_t)t*DM + base) = v;

    ss = v.x*v.x + v.y*v.y + v.z*v.z + v.w*v.w;
    r = rsqrtf(block_sum(ss, sbuf) * (1.f/DM) + 1e-6f);
    float hv[4] = { a3.x*v.x*r, a3.y*v.y*r, a3.z*v.z*r, a3.w*v.w*r };
    __align__(8) bf16 hh[4], hl[4];
    #pragma unroll
    for (int i = 0; i < 4; i++) split_bf16(hv[i], hh[i], hl[i]);
    *(uint2*)(h_hi + (size_t)t*DM + base) = *(uint2*)hh;
    *(uint2*)(h_lo + (size_t)t*DM + base) = *(uint2*)hl;
}

__global__ __launch_bounds__(256) void rmsnorm_k(
    const float* __restrict__ x, const float* __restrict__ w,
    bf16* __restrict__ o_hi, bf16* __restrict__ o_lo)
{
    __shared__ float sbuf[32];
    const int t = blockIdx.x;
    const int base = threadIdx.x * 4;
    float4 v = *(const float4*)(x + (size_t)t*DM + base);
    float4 a = *(const float4*)(w + base);
    float ss = v.x*v.x + v.y*v.y + v.z*v.z + v.w*v.w;
    float r = rsqrtf(block_sum(ss, sbuf) * (1.f/DM) + 1e-6f);
    float ov[4] = { a.x*v.x*r, a.y*v.y*r, a.z*v.z*r, a.w*v.w*r };
    __align__(8) bf16 hh[4], hl[4];
    #pragma unroll
    for (int i = 0; i < 4; i++) split_bf16(ov[i], hh[i], hl[i]);
    *(uint2*)(o_hi + (size_t)t*DM + base) = *(uint2*)hh;
    *(uint2*)(o_lo + (size_t)t*DM + base) = *(uint2*)hl;
}

// ---------------- fused weight transpose + split ----------------
struct WAll {
    const float* src[11];
    bf16* th[11];
    bf16* tl[11];
};

__global__ __launch_bounds__(256) void wconv_all(WAll wa)
{
    __shared__ float t[64][65];
    const int id = blockIdx.x;
    int m, tt;
    if (id < 1024)      { m = id >> 8; tt = id & 255; }
    else if (id < 2048) { m = 4; tt = id - 1024; }
    else if (id < 3072) { m = 5; tt = id - 2048; }
    else if (id < 4096) { m = 6; tt = id - 3072; }
    else                { int i2 = id - 4096; m = 7 + (i2 >> 1); tt = i2 & 1; }
    const int K = (m == 6) ? DFF : (m == 8 || m == 10) ? DSTATE : (m == 7 || m == 9) ? HD : DM;
    const int N = (m == 4 || m == 5) ? DFF : (m == 7 || m == 9) ? DSTATE : (m == 8 || m == 10) ? HD : DM;
    const int ntx = N / 64;
    const int n0 = (tt % ntx) * 64, k0 = (tt / ntx) * 64;
    const float* W = wa.src[m];
    bf16* Th = wa.th[m];
    bf16* Tl = wa.tl[m];
    const bool ilv = (m == 4 || m == 5);
    const int foff = (m == 5) ? 1 : 0;

    const int tid = threadIdx.x;
    {
        const int r = tid >> 2, c0 = (tid & 3) * 16;
        const float* src = W + (size_t)(k0 + r)*N + n0 + c0;
        #pragma unroll
        for (int j = 0; j < 4; j++) {
            float4 vv = *(const float4*)(src + j*4);
            t[r][c0 + j*4 + 0] = vv.x; t[r][c0 + j*4 + 1] = vv.y;
            t[r][c0 + j*4 + 2] = vv.z; t[r][c0 + j*4 + 3] = vv.w;
        }
    }
    __syncthreads();
    {
        const int n = tid >> 2, ks = (tid & 3) * 16;
        uint32_t ph[8], pl[8];
        #pragma unroll
        for (int j = 0; j < 8; j++) {
            float a = t[ks + j*2][n], c = t[ks + j*2 + 1][n];
            bf16 ha, la, hc, lc;
            split_bf16(a, ha, la); split_bf16(c, hc, lc);
            ph[j] = pk(ha, hc); pl[j] = pk(la, lc);
        }
        const size_t row_out = ilv ? (size_t)(2*(n0 + n) + foff) : (size_t)(n0 + n);
        const size_t ou = (row_out*K + k0 + ks) >> 1;
        uint32_t* dh = (uint32_t*)Th + ou;
        uint32_t* dl = (uint32_t*)Tl + ou;
        *(uint4*)(dh)     = make_uint4(ph[0], ph[1], ph[2], ph[3]);
        *(uint4*)(dh + 4) = make_uint4(ph[4], ph[5], ph[6], ph[7]);
        *(uint4*)(dl)     = make_uint4(pl[0], pl[1], pl[2], pl[3]);
        *(uint4*)(dl + 4) = make_uint4(pl[4], pl[5], pl[6], pl[7]);
    }
}

// ---------------- bf16x3 GEMM via mma.sync (128x128, 2 CTAs/SM) ----------------
// EPI: 0 none | 1 +extra | 4 +bias+extra | 5 gate/fc1 interleaved
#define GSTAGE 32768
#define GSMEM  (3*GSTAGE)

__device__ __forceinline__ uint32_t swz(int row, int chunk) {
    return (uint32_t)(row*64 + ((chunk ^ (row & 3) ^ ((row >> 2) & 1)) << 4));
}

template<int EPI, int OSPLIT>
__global__ __launch_bounds__(256) void gemm_mma(
    const bf16* __restrict__ Ahi, const bf16* __restrict__ Alo,
    const bf16* __restrict__ Bhi, const bf16* __restrict__ Blo,
    const float* __restrict__ bias, const float* __restrict__ bias2,
    const float* __restrict__ extra,
    float* __restrict__ C, bf16* __restrict__ Chi, bf16* __restrict__ Clo,
    int N, int K)
{
    extern __shared__ char smem[];
    const uint32_t sb = s2u(smem);
    const int tid = threadIdx.x;
    const int lane = tid & 31, wid = tid >> 5;
    const int wm = wid >> 2, wn = wid & 3;
    const int row0 = blockIdx.y * 128, col0 = blockIdx.x * 128;
    const int nc = K / 32;

    const int lr = tid >> 1, lc = tid & 1;
    const uint32_t off0 = swz(lr, lc), off1 = swz(lr, lc + 2);
    const bf16* gAh = Ahi + (size_t)(row0 + lr)*K + lc*8;
    const bf16* gAl = Alo + (size_t)(row0 + lr)*K + lc*8;
    const bf16* gBh = Bhi + (size_t)(col0 + lr)*K + lc*8;
    const bf16* gBl = Blo + (size_t)(col0 + lr)*K + lc*8;

    #define GLOAD(st, kc) do { \
        const uint32_t s0 = sb + (uint32_t)(st)*GSTAGE; \
        const int ko = (kc)*32; \
        CP16(s0 +          off0, gAh + ko); CP16(s0 +          off1, gAh + ko + 16); \
        CP16(s0 +  8192 + off0, gAl + ko); CP16(s0 +  8192 + off1, gAl + ko + 16); \
        CP16(s0 + 16384 + off0, gBh + ko); CP16(s0 + 16384 + off1, gBh + ko + 16); \
        CP16(s0 + 24576 + off0, gBl + ko); CP16(s0 + 24576 + off1, gBl + ko + 16); \
    } while (0)

    const int arow = wm*64 + (lane & 15);
    const int abit = lane >> 4;
    const int brow = wn*32 + (lane & 7) + ((lane >> 4) & 1)*8;
    const int bbit = (lane >> 3) & 1;

    float acc[4][4][4];
    #pragma unroll
    for (int i = 0; i < 4; i++)
        #pragma unroll
        for (int j = 0; j < 4; j++)
            #pragma unroll
            for (int d2 = 0; d2 < 4; d2++) acc[i][j][d2] = 0.f;

    GLOAD(0, 0); CP_COMMIT();
    GLOAD(1, 1); CP_COMMIT();

    for (int kc = 0; kc < nc; kc++) {
        CP_WAIT1();
        __syncthreads();
        const uint32_t s0 = sb + (uint32_t)(kc % 3)*GSTAGE;
        #pragma unroll
        for (int ks = 0; ks < 2; ks++) {
            uint32_t ah[4][4], al[4][4], bh[2][4], bl[2][4];
            #pragma unroll
            for (int mt = 0; mt < 4; mt++) {
                const uint32_t ao = swz(arow + mt*16, ks*2 + abit);
                ldm_x4(ah[mt], s0 + ao);
                ldm_x4(al[mt], s0 + 8192 + ao);
            }
            #pragma unroll
            for (int n2 = 0; n2 < 2; n2++) {
                const uint32_t bo = swz(brow + n2*16, ks*2 + bbit);
                ldm_x4(bh[n2], s0 + 16384 + bo);
                ldm_x4(bl[n2], s0 + 24576 + bo);
            }
            #pragma unroll
            for (int mt = 0; mt < 4; mt++)
                #pragma unroll
                for (int nt = 0; nt < 4; nt++) {
                    const uint32_t* ph = &bh[nt >> 1][(nt & 1)*2];
                    const uint32_t* pl = &bl[nt >> 1][(nt & 1)*2];
                    mma_bf16(acc[mt][nt], ah[mt], ph);
                    mma_bf16(acc[mt][nt], ah[mt], pl);
                    mma_bf16(acc[mt][nt], al[mt], ph);
                }
        }
        if (kc + 2 < nc) GLOAD((kc + 2) % 3, kc + 2);
        CP_COMMIT();
    }
    #undef GLOAD

    const int erow = lane >> 2;
    const int ecol = (lane & 3)*2;
    #pragma unroll
    for (int mt = 0; mt < 4; mt++)
        #pragma unroll
        for (int hf = 0; hf < 2; hf++) {
            const int row = row0 + wm*64 + mt*16 + erow + hf*8;
            #pragma unroll
            for (int nt = 0; nt < 4; nt++) {
                const int col = col0 + wn*32 + nt*8 + ecol;
                float v0 = acc[mt][nt][hf*2 + 0];
                float v1 = acc[mt][nt][hf*2 + 1];
                if (EPI == 5) {
                    const int j = col >> 1;
                    float g = v0 + bias[j];
                    float f = v1 + bias2[j];
                    g = g / (1.f + __expf(-g));
                    const float rv = g * f;
                    bf16 h0, l0; split_bf16(rv, h0, l0);
                    const size_t po = (size_t)row * (size_t)(N >> 1) + j;
                    Chi[po] = h0; Clo[po] = l0;
                    continue;
                }
                const size_t ro = (size_t)row * N + col;
                if (EPI == 1) { float2 e = *(const float2*)(extra + ro); v0 += e.x; v1 += e.y; }
                if (EPI == 4) {
                    float2 e = *(const float2*)(extra + ro);
                    v0 += bias[col] + e.x; v1 += bias[col + 1] + e.y;
                }
                if (OSPLIT) {
                    bf16 h0, l0, h1, l1;
                    split_bf16(v0, h0, l0); split_bf16(v1, h1, l1);
                    *(uint32_t*)(Chi + ro) = pk(h0, h1);
                    *(uint32_t*)(Clo + ro) = pk(l0, l1);
                } else {
                    float2 o; o.x = v0; o.y = v1;
                    *(float2*)(C + ro) = o;
                }
            }
        }
}

// ---------------- tensor-core qk silu-mlp residual (2 CTAs/SM) ----------------
#define QM_X_H 0u
#define QM_X_L 18432u
#define QM_W1H 36864u
#define QM_W1L 55296u
#define QM_W2H 73728u
#define QM_W2L 91136u
#define QM_B1  108544u
#define QM_B2  109056u
#define QM_SMEM 109312

__global__ __launch_bounds__(256, 2) void qk_mlp_mma(
    bf16* __restrict__ qkvh, bf16* __restrict__ qkvl,
    const bf16* __restrict__ w1qh, const bf16* __restrict__ w1ql,
    const bf16* __restrict__ w2qh, const bf16* __restrict__ w2ql,
    const bf16* __restrict__ w1kh, const bf16* __restrict__ w1kl,
    const bf16* __restrict__ w2kh, const bf16* __restrict__ w2kl,
    const float* __restrict__ qb1, const float* __restrict__ qb2,
    const float* __restrict__ kb1, const float* __restrict__ kb2)
{
    extern __shared__ char sm_[];
    const uint32_t sb = s2u(sm_);
    const int tid = threadIdx.x, lane = tid & 31, wid = tid >> 5;
    const int t0 = blockIdx.x * 8;
    const int seg = blockIdx.y * 1024;
    const bf16* w1h = blockIdx.y ? w1kh : w1qh;
    const bf16* w1l = blockIdx.y ? w1kl : w1ql;
    const bf16* w2h = blockIdx.y ? w2kh : w2qh;
    const bf16* w2l = blockIdx.y ? w2kl : w2ql;
    const float* b1 = blockIdx.y ? kb1 : qb1;
    const float* b2 = blockIdx.y ? kb2 : qb2;

    {
        const int r = tid >> 1, half = tid & 1;
        const uint4* s1h = (const uint4*)(w1h + r*HD + half*32);
        const uint4* s1l = (const uint4*)(w1l + r*HD + half*32);
        uint4* d1h = (uint4*)(sm_ + QM_W1H + r*144 + half*64);
        uint4* d1l = (uint4*)(sm_ + QM_W1L + r*144 + half*64);
        #pragma unroll
        for (int j = 0; j < 4; j++) { d1h[j] = s1h[j]; d1l[j] = s1l[j]; }
    }
    {
        const int r = tid >> 2, q = tid & 3;
        const uint4* s2h = (const uint4*)(w2h + r*DSTATE + q*32);
        const uint4* s2l = (const uint4*)(w2l + r*DSTATE + q*32);
        uint4* d2h = (uint4*)(sm_ + QM_W2H + r*272 + q*64);
        uint4* d2l = (uint4*)(sm_ + QM_W2L + r*272 + q*64);
        #pragma unroll
        for (int j = 0; j < 4; j++) { d2h[j] = s2h[j]; d2l[j] = s2l[j]; }
    }
    if (tid < 128) *(float*)(sm_ + QM_B1 + tid*4) = b1[tid];
    if (tid < 64)  *(float*)(sm_ + QM_B2 + tid*4) = b2[tid];
    {
        const int r = tid >> 1, half = tid & 1;
        const size_t ga = (size_t)(t0 + (r >> 4))*3072 + seg + (size_t)(r & 15)*64 + half*32;
        const uint4* sxh = (const uint4*)(qkvh + ga);
        const uint4* sxl = (const uint4*)(qkvl + ga);
        uint4* dxh = (uint4*)(sm_ + QM_X_H + r*144 + half*64);
        uint4* dxl = (uint4*)(sm_ + QM_X_L + r*144 + half*64);
        #pragma unroll
        for (int j = 0; j < 4; j++) { dxh[j] = sxh[j]; dxl[j] = sxl[j]; }
    }
    __syncthreads();

    const int m0 = wid * 16;

    float s[16][4];
    #pragma unroll
    for (int i = 0; i < 16; i++)
        #pragma unroll
        for (int e = 0; e < 4; e++) s[i][e] = 0.f;

    #pragma unroll
    for (int ks = 0; ks < 4; ks++) {
        uint32_t xh4[4], xl4[4];
        const uint32_t ao = (uint32_t)((m0 + (lane & 15))*144 + ks*32 + (lane >> 4)*16);
        ldm_x4(xh4, sb + QM_X_H + ao);
        ldm_x4(xl4, sb + QM_X_L + ao);
        #pragma unroll
        for (int n2 = 0; n2 < 8; n2++) {
            uint32_t wh4[4], wl4[4];
            const uint32_t bo = (uint32_t)((n2*16 + (lane & 7) + ((lane >> 4) & 1)*8)*144
                                           + ks*32 + ((lane >> 3) & 1)*16);
            ldm_x4(wh4, sb + QM_W1H + bo);
            ldm_x4(wl4, sb + QM_W1L + bo);
            mma_bf16(s[n2*2],   xh4, &wh4[0]);
            mma_bf16(s[n2*2],   xh4, &wl4[0]);
            mma_bf16(s[n2*2],   xl4, &wh4[0]);
            mma_bf16(s[n2*2+1], xh4, &wh4[2]);
            mma_bf16(s[n2*2+1], xh4, &wl4[2]);
            mma_bf16(s[n2*2+1], xl4, &wh4[2]);
        }
    }

    #pragma unroll
    for (int nt = 0; nt < 16; nt++)
        #pragma unroll
        for (int e = 0; e < 4; e++) {
            const int col = nt*8 + (lane & 3)*2 + (e & 1);
            float v = s[nt][e] + *(const float*)(sm_ + QM_B1 + col*4);
            s[nt][e] = v / (1.f + __expf(-v));
        }

    float o[8][4];
    #pragma unroll
    for (int i = 0; i < 8; i++)
        #pragma unroll
        for (int e = 0; e < 4; e++) o[i][e] = 0.f;

    #pragma unroll
    for (int ks2 = 0; ks2 < 8; ks2++) {
        uint32_t pah[4], pal[4];
        {
            bf16 h0,l0,h1,l1;
            split_bf16(s[2*ks2][0],h0,l0);   split_bf16(s[2*ks2][1],h1,l1);
            pah[0] = pk(h0,h1); pal[0] = pk(l0,l1);
            split_bf16(s[2*ks2][2],h0,l0);   split_bf16(s[2*ks2][3],h1,l1);
            pah[1] = pk(h0,h1); pal[1] = pk(l0,l1);
            split_bf16(s[2*ks2+1][0],h0,l0); split_bf16(s[2*ks2+1][1],h1,l1);
            pah[2] = pk(h0,h1); pal[2] = pk(l0,l1);
            split_bf16(s[2*ks2+1][2],h0,l0); split_bf16(s[2*ks2+1][3],h1,l1);
            pah[3] = pk(h0,h1); pal[3] = pk(l0,l1);
        }
        #pragma unroll
        for (int n2 = 0; n2 < 4; n2++) {
            uint32_t wh4[4], wl4[4];
            const uint32_t bo = (uint32_t)((n2*16 + (lane & 7) + ((lane >> 4) & 1)*8)*272
                                           + ks2*32 + ((lane >> 3) & 1)*16);
            ldm_x4(wh4, sb + QM_W2H + bo);
            ldm_x4(wl4, sb + QM_W2L + bo);
            mma_bf16(o[n2*2],   pah, &wh4[0]);
            mma_bf16(o[n2*2],   pah, &wl4[0]);
            mma_bf16(o[n2*2],   pal, &wh4[0]);
            mma_bf16(o[n2*2+1], pah, &wh4[2]);
            mma_bf16(o[n2*2+1], pah, &wl4[2]);
            mma_bf16(o[n2*2+1], pal, &wh4[2]);
        }
    }

    #pragma unroll
    for (int nt = 0; nt < 8; nt++)
        #pragma unroll
        for (int hf = 0; hf < 2; hf++) {
            const int rl = (lane >> 2) + hf*8;
            const int c0 = nt*8 + (lane & 3)*2;
            const int rX = m0 + rl;
            const float rs0 = __bfloat162float(*(const bf16*)(sm_ + QM_X_H + rX*144 + c0*2))
                            + __bfloat162float(*(const bf16*)(sm_ + QM_X_L + rX*144 + c0*2));
            const float rs1 = __bfloat162float(*(const bf16*)(sm_ + QM_X_H + rX*144 + c0*2 + 2))
                            + __bfloat162float(*(const bf16*)(sm_ + QM_X_L + rX*144 + c0*2 + 2));
            const float v0 = o[nt][hf*2 + 0] + *(const float*)(sm_ + QM_B2 + c0*4)     + rs0;
            const float v1 = o[nt][hf*2 + 1] + *(const float*)(sm_ + QM_B2 + c0*4 + 4) + rs1;
            bf16 h0, l0, h1, l1;
            split_bf16(v0, h0, l0); split_bf16(v1, h1, l1);
            const size_t ga = (size_t)(t0 + wid)*3072 + seg + (size_t)rl*64 + c0;
            *(uint32_t*)(qkvh + ga) = pk(h0, h1);
            *(uint32_t*)(qkvl + ga) = pk(l0, l1);
        }
}

// ---------------- pipelined tensor-core flash attention ----------------
#define FA_QH 0u
#define FA_QL 18432u
#define FA_S0 36864u
#define FA_STG 36864u
#define FA_SMEM 110592

__global__ __launch_bounds__(256, 2) void flash_mma(
    const bf16* __restrict__ QKVh, const bf16* __restrict__ QKVl,
    bf16* __restrict__ Ohi, bf16* __restrict__ Olo)
{
    extern __shared__ char sm_[];
    const uint32_t sb = s2u(sm_);
    const int tid = threadIdx.x;
    const int lane = tid & 31, wid = tid >> 5;
    const int qt = (int)gridDim.x - 1 - (int)blockIdx.x;
    const int h = blockIdx.y, b = blockIdx.z;
    const int qb = qt * 128;
    const int m0 = wid * 16;

    {
        const int r = tid >> 1;
        const int half = tid & 1;
        const size_t go = (size_t)(b*SS_ + qb + r)*3072 + h*64 + half*32;
        const uint4* srcH = (const uint4*)(QKVh + go);
        const uint4* srcL = (const uint4*)(QKVl + go);
        uint4* dstH = (uint4*)(sm_ + FA_QH + r*144 + half*64);
        uint4* dstL = (uint4*)(sm_ + FA_QL + r*144 + half*64);
        #pragma unroll
        for (int j = 0; j < 4; j++) { dstH[j] = srcH[j]; dstL[j] = srcL[j]; }
    }

    const int klr = tid >> 2, klq = tid & 3;
    #define LOADKV(st, kjj) do { \
        const uint32_t s0 = sb + FA_S0 + (uint32_t)(st)*FA_STG; \
        const uint32_t d = (uint32_t)(klr*144 + klq*32); \
        const size_t gk = (size_t)(b*SS_ + (kjj)*64 + klr)*3072 + 1024 + h*64 + klq*16; \
        CP16(s0 + d,               QKVh + gk);        CP16(s0 + d + 16,          QKVh + gk + 8); \
        CP16(s0 + 9216u + d,       QKVl + gk);        CP16(s0 + 9216u + d + 16,  QKVl + gk + 8); \
        CP16(s0 + 18432u + d,      QKVh + gk + 1024); CP16(s0 + 18432u + d + 16, QKVh + gk + 1032); \
        CP16(s0 + 27648u + d,      QKVl + gk + 1024); CP16(s0 + 27648u + d + 16, QKVl + gk + 1032); \
    } while (0)

    float mstate[2] = {-1e30f, -1e30f};
    float lsum[2]   = {0.f, 0.f};
    float o[8][4];
    #pragma unroll
    for (int i = 0; i < 8; i++)
        #pragma unroll
        for (int e = 0; e < 4; e++) o[i][e] = 0.f;

    const int nk = 2*qt + 2;
    LOADKV(0, 0); CP_COMMIT();

    for (int kj = 0; kj < nk; kj++) {
        CP_WAIT0();
        __syncthreads();
        if (kj + 1 < nk) { LOADKV((kj + 1) & 1, kj + 1); CP_COMMIT(); }
        const uint32_t st = sb + FA_S0 + (uint32_t)(kj & 1)*FA_STG;

        if (kj*64 <= qb + m0 + 15) {
            float s[8][4];
            #pragma unroll
            for (int i = 0; i < 8; i++)
                #pragma unroll
                for (int e = 0; e < 4; e++) s[i][e] = 0.f;

            #pragma unroll
            for (int ks = 0; ks < 4; ks++) {
                uint32_t qh4[4], ql4[4];
                const uint32_t ao = (uint32_t)((m0 + (lane & 15))*144 + ks*32 + (lane >> 4)*16);
                ldm_x4(qh4, sb + FA_QH + ao);
                ldm_x4(ql4, sb + FA_QL + ao);
                #pragma unroll
                for (int n2 = 0; n2 < 4; n2++) {
                    uint32_t kh4[4], kl4[4];
                    const uint32_t bo = (uint32_t)((n2*16 + (lane & 7) + ((lane >> 4) & 1)*8)*144
                                                   + ks*32 + ((lane >> 3) & 1)*16);
                    ldm_x4(kh4, st + bo);
                    ldm_x4(kl4, st + 9216u + bo);
                    mma_bf16(s[n2*2],   qh4, &kh4[0]);
                    mma_bf16(s[n2*2],   qh4, &kl4[0]);
                    mma_bf16(s[n2*2],   ql4, &kh4[0]);
                    mma_bf16(s[n2*2+1], qh4, &kh4[2]);
                    mma_bf16(s[n2*2+1], qh4, &kl4[2]);
                    mma_bf16(s[n2*2+1], ql4, &kh4[2]);
                }
            }

            const bool need_mask = (kj*64 + 63 > qb + m0);
            #pragma unroll
            for (int nt = 0; nt < 8; nt++)
                #pragma unroll
                for (int e = 0; e < 4; e++) {
                    float val = s[nt][e] * 0.125f;
                    if (need_mask) {
                        const int col = kj*64 + nt*8 + (lane & 3)*2 + (e & 1);
                        const int row = qb + m0 + (lane >> 2) + (e >> 1)*8;
                        if (col > row) val = -1e30f;
                    }
                    s[nt][e] = val;
                }

            float mx[2] = {-1e30f, -1e30f};
            #pragma unroll
            for (int nt = 0; nt < 8; nt++) {
                mx[0] = fmaxf(mx[0], fmaxf(s[nt][0], s[nt][1]));
                mx[1] = fmaxf(mx[1], fmaxf(s[nt][2], s[nt][3]));
            }
            #pragma unroll
            for (int hf = 0; hf < 2; hf++) {
                mx[hf] = fmaxf(mx[hf], __shfl_xor_sync(0xffffffffu, mx[hf], 1));
                mx[hf] = fmaxf(mx[hf], __shfl_xor_sync(0xffffffffu, mx[hf], 2));
            }
            float al2[2];
            #pragma unroll
            for (int hf = 0; hf < 2; hf++) {
                const float mn = fmaxf(fmaxf(mstate[hf], mx[hf]), -1e20f);
                al2[hf] = __expf(mstate[hf] - mn);
                mstate[hf] = mn;
            }
            float sum[2] = {0.f, 0.f};
            #pragma unroll
            for (int nt = 0; nt < 8; nt++)
                #pragma unroll
                for (int e = 0; e < 4; e++) {
                    const float p = __expf(s[nt][e] - mstate[e >> 1]);
                    s[nt][e] = p;
                    sum[e >> 1] += p;
                }
            #pragma unroll
            for (int hf = 0; hf < 2; hf++) {
                sum[hf] += __shfl_xor_sync(0xffffffffu, sum[hf], 1);
                sum[hf] += __shfl_xor_sync(0xffffffffu, sum[hf], 2);
                lsum[hf] = lsum[hf]*al2[hf] + sum[hf];
            }
            #pragma unroll
            for (int nt = 0; nt < 8; nt++)
                #pragma unroll
                for (int e = 0; e < 4; e++) o[nt][e] *= al2[e >> 1];

            #pragma unroll
            for (int ks2 = 0; ks2 < 4; ks2++) {
                uint32_t pah[4], pal[4];
                {
                    bf16 h0,l0,h1,l1;
                    split_bf16(s[2*ks2][0],h0,l0);   split_bf16(s[2*ks2][1],h1,l1);
                    pah[0] = pk(h0,h1); pal[0] = pk(l0,l1);
                    split_bf16(s[2*ks2][2],h0,l0);   split_bf16(s[2*ks2][3],h1,l1);
                    pah[1] = pk(h0,h1); pal[1] = pk(l0,l1);
                    split_bf16(s[2*ks2+1][0],h0,l0); split_bf16(s[2*ks2+1][1],h1,l1);
                    pah[2] = pk(h0,h1); pal[2] = pk(l0,l1);
                    split_bf16(s[2*ks2+1][2],h0,l0); split_bf16(s[2*ks2+1][3],h1,l1);
                    pah[3] = pk(h0,h1); pal[3] = pk(l0,l1);
                }
                #pragma unroll
                for (int dn2 = 0; dn2 < 4; dn2++) {
                    uint32_t vh4[4], vl4[4];
                    const uint32_t vo = (uint32_t)((ks2*16 + (lane & 7) + ((lane >> 3) & 1)*8)*144
                                                   + (dn2*16 + ((lane >> 4) & 1)*8)*2);
                    ldm_x4t(vh4, st + 18432u + vo);
                    ldm_x4t(vl4, st + 27648u + vo);
                    mma_bf16(o[dn2*2],   pah, &vh4[0]);
                    mma_bf16(o[dn2*2],   pah, &vl4[0]);
                    mma_bf16(o[dn2*2],   pal, &vh4[0]);
                    mma_bf16(o[dn2*2+1], pah, &vh4[2]);
                    mma_bf16(o[dn2*2+1], pah, &vl4[2]);
                    mma_bf16(o[dn2*2+1], pal, &vh4[2]);
                }
            }
        }
    }
    #undef LOADKV

    const float inv0 = 1.f / lsum[0];
    const float inv1 = 1.f / lsum[1];
    #pragma unroll
    for (int nt = 0; nt < 8; nt++)
        #pragma unroll
        for (int hf = 0; hf < 2; hf++) {
            const float inv = hf ? inv1 : inv0;
            const float v0 = o[nt][hf*2 + 0] * inv;
            const float v1 = o[nt][hf*2 + 1] * inv;
            bf16 h0, l0, h1, l1;
            split_bf16(v0, h0, l0); split_bf16(v1, h1, l1);
            const int row = qb + m0 + (lane >> 2) + hf*8;
            const int d0 = nt*8 + (lane & 3)*2;
            const size_t ro = ((size_t)(b*SS_ + row)*NH + h)*HD + d0;
            *(uint32_t*)(Ohi + ro) = pk(h0, h1);
            *(uint32_t*)(Olo + ro) = pk(l0, l1);
        }
}

// ---------------- launcher ----------------
extern "C" void kernel_launch(void* const* d_in, const int* in_sizes, int n_in,
                              void* d_out, int out_size)
{
    const float* x       = (const float*)d_in[0];
    const float* norm1_w = (const float*)d_in[2];
    const float* norm2_w = (const float*)d_in[3];
    const float* norm3_w = (const float*)d_in[4];
    const float* mlpn_w  = (const float*)d_in[5];
    const float* wq      = (const float*)d_in[6];
    const float* wk      = (const float*)d_in[7];
    const float* wv      = (const float*)d_in[8];
    const float* wo      = (const float*)d_in[9];
    const float* qs_w1   = (const float*)d_in[10];
    const float* qs_b1   = (const float*)d_in[11];
    const float* qs_w2   = (const float*)d_in[12];
    const float* qs_b2   = (const float*)d_in[13];
    const float* ks_w1   = (const float*)d_in[14];
    const float* ks_b1   = (const float*)d_in[15];
    const float* ks_w2   = (const float*)d_in[16];
    const float* ks_b2   = (const float*)d_in[17];
    const float* fc1_w   = (const float*)d_in[18];
    const float* fc1_b   = (const float*)d_in[19];
    const float* fc2_w   = (const float*)d_in[20];
    const float* fc2_b   = (const float*)d_in[21];
    const float* gate_w  = (const float*)d_in[22];
    const float* gate_b  = (const float*)d_in[23];
    float* out = (float*)d_out;

    bf16 *qkvh, *qkvl, *hh, *hl, *ah, *al, *f2h, *f2l;
    bf16 *wqkvh, *wqkvl, *woh, *wol, *gf1h, *gf1l, *fch, *fcl;
    bf16 *w1qh, *w1ql, *w2qh, *w2ql, *w1kh, *w1kl, *w2kh, *w2kl;
    cudaGetSymbolAddress((void**)&qkvh, g_qkv_hi);   cudaGetSymbolAddress((void**)&qkvl, g_qkv_lo);
    cudaGetSymbolAddress((void**)&hh,  g_h_hi);      cudaGetSymbolAddress((void**)&hl,  g_h_lo);
    cudaGetSymbolAddress((void**)&ah,  g_attn_hi);   cudaGetSymbolAddress((void**)&al,  g_attn_lo);
    cudaGetSymbolAddress((void**)&f2h, g_ff2_hi);    cudaGetSymbolAddress((void**)&f2l, g_ff2_lo);
    cudaGetSymbolAddress((void**)&wqkvh, g_wqkvT_hi); cudaGetSymbolAddress((void**)&wqkvl, g_wqkvT_lo);
    cudaGetSymbolAddress((void**)&woh, g_woT_hi);    cudaGetSymbolAddress((void**)&wol, g_woT_lo);
    cudaGetSymbolAddress((void**)&gf1h, g_gf1T_hi);  cudaGetSymbolAddress((void**)&gf1l, g_gf1T_lo);
    cudaGetSymbolAddress((void**)&fch, g_f2T_hi);    cudaGetSymbolAddress((void**)&fcl, g_f2T_lo);
    cudaGetSymbolAddress((void**)&w1qh, g_w1qT_hi);  cudaGetSymbolAddress((void**)&w1ql, g_w1qT_lo);
    cudaGetSymbolAddress((void**)&w2qh, g_w2qT_hi);  cudaGetSymbolAddress((void**)&w2ql, g_w2qT_lo);
    cudaGetSymbolAddress((void**)&w1kh, g_w1kT_hi);  cudaGetSymbolAddress((void**)&w1kl, g_w1kT_lo);
    cudaGetSymbolAddress((void**)&w2kh, g_w2kT_hi);  cudaGetSymbolAddress((void**)&w2kl, g_w2kT_lo);

    cudaFuncSetAttribute(gemm_mma<0,1>, cudaFuncAttributeMaxDynamicSharedMemorySize, GSMEM);
    cudaFuncSetAttribute(gemm_mma<1,0>, cudaFuncAttributeMaxDynamicSharedMemorySize, GSMEM);
    cudaFuncSetAttribute(gemm_mma<5,0>, cudaFuncAttributeMaxDynamicSharedMemorySize, GSMEM);
    cudaFuncSetAttribute(gemm_mma<4,0>, cudaFuncAttributeMaxDynamicSharedMemorySize, GSMEM);
    cudaFuncSetAttribute(qk_mlp_mma, cudaFuncAttributeMaxDynamicSharedMemorySize, QM_SMEM);
    cudaFuncSetAttribute(flash_mma, cudaFuncAttributeMaxDynamicSharedMemorySize, FA_SMEM);

    // launch 1: all weight converts
    WAll wa;
    wa.src[0] = wq;     wa.th[0] = wqkvh;           wa.tl[0] = wqkvl;
    wa.src[1] = wk;     wa.th[1] = wqkvh + DM*DM;   wa.tl[1] = wqkvl + DM*DM;
    wa.src[2] = wv;     wa.th[2] = wqkvh + 2*DM*DM; wa.tl[2] = wqkvl + 2*DM*DM;
    wa.src[3] = wo;     wa.th[3] = woh;             wa.tl[3] = wol;
    wa.src[4] = gate_w; wa.th[4] = gf1h;            wa.tl[4] = gf1l;
    wa.src[5] = fc1_w;  wa.th[5] = gf1h;            wa.tl[5] = gf1l;
    wa.src[6] = fc2_w;  wa.th[6] = fch;             wa.tl[6] = fcl;
    wa.src[7] = qs_w1;  wa.th[7] = w1qh;            wa.tl[7] = w1ql;
    wa.src[8] = qs_w2;  wa.th[8] = w2qh;            wa.tl[8] = w2ql;
    wa.src[9] = ks_w1;  wa.th[9] = w1kh;            wa.tl[9] = w1kl;
    wa.src[10] = ks_w2; wa.th[10] = w2kh;           wa.tl[10] = w2kl;
    wconv_all<<<4104, 256>>>(wa);

    // launch 2: mamba stages + pre-attn norm
    norm3_fused<<<NT, 256>>>(x, norm1_w, norm2_w, norm3_w, out, hh, hl);

    // launch 3: fused qkv projection -> token-major [NT, 3072] hi/lo
    gemm_mma<0,1><<<dim3(3*DM/128, NT/128), 256, GSMEM>>>(
        hh, hl, wqkvh, wqkvl, nullptr, nullptr, nullptr, nullptr, qkvh, qkvl, 3*DM, DM);

    // launch 4: per-head SiLU-MLP residual on q,k (tensor cores)
    qk_mlp_mma<<<dim3(NT/8, 2), 256, QM_SMEM>>>(qkvh, qkvl,
        w1qh, w1ql, w2qh, w2ql, w1kh, w1kl, w2kh, w2kl,
        qs_b1, qs_b2, ks_b1, ks_b2);

    // launch 5: causal attention (pipelined)
    flash_mma<<<dim3(SS_/128, NH, BB), 256, FA_SMEM>>>(qkvh, qkvl, ah, al);

    // launch 6: out projection + residual
    gemm_mma<1,0><<<dim3(DM/128, NT/128), 256, GSMEM>>>(
        ah, al, woh, wol, nullptr, nullptr, out, out, nullptr, nullptr, DM, DM);

    // launch 7: mlp norm
    rmsnorm_k<<<NT, 256>>>(out, mlpn_w, hh, hl);

    // launch 8: fused gate+fc1+silu-mul -> f2 hi/lo
    gemm_mma<5,0><<<dim3(2*DFF/128, NT/128), 256, GSMEM>>>(
        hh, hl, gf1h, gf1l, gate_b, fc1_b, nullptr, nullptr, f2h, f2l, 2*DFF, DM);

    // launch 9: fc2 + bias + residual
    gemm_mma<4,0><<<dim3(DM/128, NT/128), 256, GSMEM>>>(
        f2h, f2l, fch, fcl, fc2_b, nullptr, out, out, nullptr, nullptr, DM, DFF);
}